// round 15
// baseline (speedup 1.0000x reference)
#include <cuda_runtime.h>
#include <cuda_fp16.h>
#include <math.h>

#define NN 32768
#define EE 262144
#define FF 64
#define PSC 9
#define ZZ 10
#define NF (NN*FF)
#define HS 66   // padded row stride (floats): bank shift 4*66 mod 32 = 8 -> conflict-free h loads

typedef unsigned long long u64;

// ---------------- device scratch ----------------
__device__ float g_skip_s[NF];
__device__ float g_skip_v[3*NF];
__device__ float g_sup[NF];
__device__ float g_vup[3*NF];
__device__ float g_agg_s[NF];
__device__ float g_agg_v[3*NF];
__device__ __half g_wh[(size_t)EE*320];   // per-edge TP path weights [E,5,64], fp16
__device__ __half g_wssh[ZZ*4096];        // fp16 per-species skip weights
__device__ __half g_wsvh[ZZ*4096];

// ---------------- f32x2 packed-math helpers ----------------
__device__ __forceinline__ u64 pack2(float x) {
    u64 r; asm("mov.b64 %0, {%1, %1};" : "=l"(r) : "f"(x)); return r;
}
__device__ __forceinline__ u64 fma2(u64 a, u64 b, u64 c) {
    u64 d; asm("fma.rn.f32x2 %0, %1, %2, %3;" : "=l"(d) : "l"(a), "l"(b), "l"(c)); return d;
}
__device__ __forceinline__ float2 unpk(u64 a) {
    float2 f; asm("mov.b64 {%0, %1}, %2;" : "=f"(f.x), "=f"(f.y) : "l"(a)); return f;
}
__device__ __forceinline__ float silu(float x) { return x / (1.f + __expf(-x)); }

__global__ void zero_agg() {
    int stride = gridDim.x * blockDim.x;
    int t = blockIdx.x * blockDim.x + threadIdx.x;
    for (int i = t; i < NF; i += stride) g_agg_s[i] = 0.f;
    for (int i = t; i < 3*NF; i += stride) g_agg_v[i] = 0.f;
}

// convert per-species skip weights to fp16 (320 KB total, trivial)
__global__ void convert_skip(const float* __restrict__ Wss, const float* __restrict__ Wsv) {
    int i = blockIdx.x * 256 + threadIdx.x;
    if (i < ZZ*4096) {
        g_wssh[i] = __float2half(Wss[i]);
        g_wsvh[i] = __float2half(Wsv[i]);
    }
}

// ---------------- kernel A: per-species skip linear (fp16 weights) + linear_up ----------------
__global__ void __launch_bounds__(512)
node_pre(const float* __restrict__ nf,
         const float* __restrict__ Wus,
         const float* __restrict__ Wuv,
         const int*   __restrict__ species) {
    __shared__ float sWus[FF*FF], sWuv[FF*FF];
    __shared__ float s_sh[8][FF];
    __shared__ float v_sh[8][3*FF];
    int tid = threadIdx.x;
    for (int i = tid; i < FF*FF; i += 512) { sWus[i] = Wus[i]; sWuv[i] = Wuv[i]; }
    __syncthreads();
    int g = tid & 63, grp = tid >> 6;
    int bar = grp + 1;
    int group_id = blockIdx.x * 8 + grp;
    int totalGroups = gridDim.x * 8;
    for (int n = group_id; n < NN; n += totalGroups) {
        const float* row = nf + (size_t)n * 256;
        s_sh[grp][g]        = row[g];
        v_sh[grp][g]        = row[64 + g];
        v_sh[grp][64 + g]   = row[128 + g];
        v_sh[grp][128 + g]  = row[192 + g];
        asm volatile("bar.sync %0, 64;" :: "r"(bar) : "memory");
        int z = species[n];
        const __half* wssz = g_wssh + z * 4096;
        const __half* wsvz = g_wsvh + z * 4096;
        float ks = 0.f, kv0 = 0.f, kv1 = 0.f, kv2 = 0.f;
        float us = 0.f, uv0 = 0.f, uv1 = 0.f, uv2 = 0.f;
        #pragma unroll 8
        for (int f = 0; f < FF; f++) {
            float sv = s_sh[grp][f];
            float a0 = v_sh[grp][f*3], a1 = v_sh[grp][f*3+1], a2 = v_sh[grp][f*3+2];
            float w1 = __half2float(__ldg(wssz + f*64 + g));
            float w2 = __half2float(__ldg(wsvz + f*64 + g));
            float w3 = sWus[f*64 + g];
            float w4 = sWuv[f*64 + g];
            ks  += sv * w1; kv0 += a0 * w2; kv1 += a1 * w2; kv2 += a2 * w2;
            us  += sv * w3; uv0 += a0 * w4; uv1 += a1 * w4; uv2 += a2 * w4;
        }
        const float invZ = 0.039528471f;
        const float inv  = 0.125f;
        g_skip_s[n*64 + g]          = ks  * invZ;
        g_skip_v[0*NF + n*64 + g]   = kv0 * invZ;
        g_skip_v[1*NF + n*64 + g]   = kv1 * invZ;
        g_skip_v[2*NF + n*64 + g]   = kv2 * invZ;
        g_sup[n*64 + g]             = us  * inv;
        g_vup[0*NF + n*64 + g]      = uv0 * inv;
        g_vup[1*NF + n*64 + g]      = uv1 * inv;
        g_vup[2*NF + n*64 + g]      = uv2 * inv;
        asm volatile("bar.sync %0, 64;" :: "r"(bar) : "memory");
    }
}

// ---------------- kernel B1: radial MLP (conflict-free HS=66) ----------------
#define MLP_SMEM_FLOATS (512 + 4096 + 4096 + 20480 + 2048 + 256*HS)

__device__ __forceinline__ void kstep(const float* __restrict__ hin, int e0, int k,
                                      const float* __restrict__ wrow, u64 acc[4][4]) {
    u64 hp[4];
    #pragma unroll
    for (int ee = 0; ee < 4; ee++) hp[ee] = pack2(hin[(e0+ee)*HS + k]);
    ulonglong2 wa = *(const ulonglong2*)(wrow);
    ulonglong2 wb = *(const ulonglong2*)(wrow + 4);
    #pragma unroll
    for (int ee = 0; ee < 4; ee++) {
        acc[0][ee] = fma2(hp[ee], wa.x, acc[0][ee]);
        acc[1][ee] = fma2(hp[ee], wa.y, acc[1][ee]);
        acc[2][ee] = fma2(hp[ee], wb.x, acc[2][ee]);
        acc[3][ee] = fma2(hp[ee], wb.y, acc[3][ee]);
    }
}

__device__ __forceinline__ void zacc(u64 acc[4][4]) {
    #pragma unroll
    for (int gp = 0; gp < 4; gp++)
        #pragma unroll
        for (int ee = 0; ee < 4; ee++) acc[gp][ee] = 0ull;
}

// float2 stores (rows are 8B-aligned with HS=66)
__device__ __forceinline__ void write_silu(u64 acc[4][4], float* h, int e0, int g0, float scale) {
    #pragma unroll
    for (int ee = 0; ee < 4; ee++) {
        float2 a = unpk(acc[0][ee]), b = unpk(acc[1][ee]);
        float2 c = unpk(acc[2][ee]), d = unpk(acc[3][ee]);
        float* dst = h + (e0+ee)*HS + g0;
        *(float2*)(dst)     = make_float2(silu(a.x*scale), silu(a.y*scale));
        *(float2*)(dst + 2) = make_float2(silu(b.x*scale), silu(b.y*scale));
        *(float2*)(dst + 4) = make_float2(silu(c.x*scale), silu(c.y*scale));
        *(float2*)(dst + 6) = make_float2(silu(d.x*scale), silu(d.y*scale));
    }
}

__global__ void __launch_bounds__(512)
mlp_kernel(const float* __restrict__ re,
           const float* __restrict__ W1,
           const float* __restrict__ W2,
           const float* __restrict__ W3,
           const float* __restrict__ W4) {
    extern __shared__ float sm[];
    float* sW1 = sm;
    float* sW2 = sW1 + 512;
    float* sW3 = sW2 + 4096;
    float* sW4 = sW3 + 4096;
    float* sRE = sW4 + 20480;
    float* h   = sRE + 2048;
    int tid = threadIdx.x;
    for (int i = tid; i < 512;   i += 512) sW1[i] = W1[i];
    for (int i = tid; i < 4096;  i += 512) { sW2[i] = W2[i]; sW3[i] = W3[i]; }
    for (int i = tid; i < 20480; i += 512) sW4[i] = W4[i];

    int e_base = blockIdx.x * 256;
    for (int i = tid; i < 2048; i += 512) sRE[i] = re[(size_t)e_base*8 + i];
    __syncthreads();

    int cj = tid & 7, ei = tid >> 3;
    int g0 = cj * 8, e0 = ei * 4;

    u64 acc[4][4];

    zacc(acc);
    #pragma unroll
    for (int k = 0; k < 8; k++) {
        u64 hp[4];
        #pragma unroll
        for (int ee = 0; ee < 4; ee++) hp[ee] = pack2(sRE[(e0+ee)*8 + k]);
        ulonglong2 wa = *(const ulonglong2*)(sW1 + k*64 + g0);
        ulonglong2 wb = *(const ulonglong2*)(sW1 + k*64 + g0 + 4);
        #pragma unroll
        for (int ee = 0; ee < 4; ee++) {
            acc[0][ee] = fma2(hp[ee], wa.x, acc[0][ee]);
            acc[1][ee] = fma2(hp[ee], wa.y, acc[1][ee]);
            acc[2][ee] = fma2(hp[ee], wb.x, acc[2][ee]);
            acc[3][ee] = fma2(hp[ee], wb.y, acc[3][ee]);
        }
    }
    write_silu(acc, h, e0, g0, 0.35355339f);
    __syncthreads();

    zacc(acc);
    #pragma unroll 8
    for (int k = 0; k < 64; k++) kstep(h, e0, k, sW2 + k*64 + g0, acc);
    __syncthreads();
    write_silu(acc, h, e0, g0, 0.125f);
    __syncthreads();

    zacc(acc);
    #pragma unroll 8
    for (int k = 0; k < 64; k++) kstep(h, e0, k, sW3 + k*64 + g0, acc);
    __syncthreads();
    write_silu(acc, h, e0, g0, 0.125f);
    __syncthreads();

    // layer 4: 5 path slices of W4, write g_wh (fp16)
    #pragma unroll
    for (int p = 0; p < 5; p++) {
        zacc(acc);
        #pragma unroll 8
        for (int k = 0; k < 64; k++) kstep(h, e0, k, sW4 + k*320 + p*64 + g0, acc);
        #pragma unroll
        for (int ee = 0; ee < 4; ee++) {
            float2 a = unpk(acc[0][ee]), b = unpk(acc[1][ee]);
            float2 c = unpk(acc[2][ee]), d = unpk(acc[3][ee]);
            __half2 h0 = __floats2half2_rn(a.x*0.125f, a.y*0.125f);
            __half2 h1 = __floats2half2_rn(b.x*0.125f, b.y*0.125f);
            __half2 h2 = __floats2half2_rn(c.x*0.125f, c.y*0.125f);
            __half2 h3 = __floats2half2_rn(d.x*0.125f, d.y*0.125f);
            __half2* dst = (__half2*)(g_wh + (size_t)(e_base + e0 + ee)*320 + p*64 + g0);
            uint4 pk;
            pk.x = *(unsigned*)&h0; pk.y = *(unsigned*)&h1;
            pk.z = *(unsigned*)&h2; pk.w = *(unsigned*)&h3;
            *(uint4*)dst = pk;
        }
    }
}

// ---------------- kernel B2: tensor product + scatter (R13 exact) ----------------
__global__ void tp_scatter(const float* __restrict__ vectors,
                           const int* __restrict__ senders,
                           const int* __restrict__ receivers) {
    int t = blockIdx.x * 256 + threadIdx.x;
    int e = t >> 6, g = t & 63;
    float vx = __ldg(vectors + e*3), vy = __ldg(vectors + e*3 + 1), vz = __ldg(vectors + e*3 + 2);
    float rn = 1.f / (sqrtf(vx*vx + vy*vy + vz*vz) + 1e-9f);
    float y0 = vx * rn, y1 = vy * rn, y2 = vz * rn;

    const __half* wrow = g_wh + (size_t)e*320 + g;
    float w0  = __half2float(wrow[0]);
    float w1a = __half2float(wrow[64]);
    float w2a = __half2float(wrow[128]);
    float w3a = __half2float(wrow[192]);
    float w4a = __half2float(wrow[256]);

    int sn = __ldg(senders + e), rc = __ldg(receivers + e);
    float ss = g_sup[sn*64 + g];
    float b0 = g_vup[0*NF + sn*64 + g];
    float b1 = g_vup[1*NF + sn*64 + g];
    float b2 = g_vup[2*NF + sn*64 + g];
    float dot = b0*y0 + b1*y1 + b2*y2;
    float c0 = b1*y2 - b2*y1;
    float c1 = b2*y0 - b0*y2;
    float c2 = b0*y1 - b1*y0;
    const float is2 = 0.70710678f;
    float ms  = (w0*ss + w3a*dot) * 0.25f;
    float mv0 = (w1a*y0 + w2a*b0 + w4a*c0*is2) * 0.25f;
    float mv1 = (w1a*y1 + w2a*b1 + w4a*c1*is2) * 0.25f;
    float mv2 = (w1a*y2 + w2a*b2 + w4a*c2*is2) * 0.25f;
    atomicAdd(&g_agg_s[rc*64 + g], ms);
    atomicAdd(&g_agg_v[0*NF + rc*64 + g], mv0);
    atomicAdd(&g_agg_v[1*NF + rc*64 + g], mv1);
    atomicAdd(&g_agg_v[2*NF + rc*64 + g], mv2);
}

// ---------------- kernel C: node_post (R8 exact, 512 thr) ----------------
#define POST_SMEM_FLOATS (4*4096 + 8*576)
__global__ void __launch_bounds__(512)
node_post(const float* __restrict__ Wds,
          const float* __restrict__ Wdv,
          const float* __restrict__ Wsc,
          const float* __restrict__ Wps,
          const float* __restrict__ Wpv,
          const float* __restrict__ Wout,
          const int*   __restrict__ species,
          float* __restrict__ out) {
    extern __shared__ float sm[];
    float* sWds = sm;
    float* sWdv = sm + 4096;
    float* sWps = sm + 8192;
    float* sWpv = sm + 12288;
    float* buf  = sm + 16384;
    int tid = threadIdx.x;
    for (int i = tid; i < 4096; i += 512) {
        sWds[i] = Wds[i]; sWdv[i] = Wdv[i]; sWps[i] = Wps[i]; sWpv[i] = Wpv[i];
    }
    __syncthreads();
    int g = tid & 63, grp = tid >> 6, bar = grp + 1;
    float* ags = buf + grp * 576;
    float* agv = ags + 64;
    float* so  = agv + 192;
    float* vo  = so + 64;
    float* red = vo + 192;
    int group_id = blockIdx.x * 8 + grp;
    int totalGroups = gridDim.x * 8;
    for (int n = group_id; n < NN; n += totalGroups) {
        ags[g]       = g_agg_s[n*64 + g];
        agv[g]       = g_agg_v[0*NF + n*64 + g];
        agv[64 + g]  = g_agg_v[1*NF + n*64 + g];
        agv[128 + g] = g_agg_v[2*NF + n*64 + g];
        asm volatile("bar.sync %0, 64;" :: "r"(bar) : "memory");

        float sd = 0.f, vd0 = 0.f, vd1 = 0.f, vd2 = 0.f;
        #pragma unroll 8
        for (int f = 0; f < 64; f++) {
            float a  = ags[f];
            float a0 = agv[f], a1 = agv[64 + f], a2 = agv[128 + f];
            float w1 = sWds[f*64 + g], w2 = sWdv[f*64 + g];
            sd += a * w1; vd0 += a0 * w2; vd1 += a1 * w2; vd2 += a2 * w2;
        }
        sd *= 0.125f; vd0 *= 0.125f; vd1 *= 0.125f; vd2 *= 0.125f;

        int z = species[n];
        const float* wz = Wsc + z * (PSC*64) + g;
        float q0 = __ldg(wz),       q1 = __ldg(wz + 64),  q2 = __ldg(wz + 128);
        float q3 = __ldg(wz + 192), q4 = __ldg(wz + 256), q5 = __ldg(wz + 320);
        float q6 = __ldg(wz + 384), q7 = __ldg(wz + 448), q8 = __ldg(wz + 512);
        float vn2 = vd0*vd0 + vd1*vd1 + vd2*vd2;
        float s2  = sd * sd;
        float sout = q0*sd + q1*s2 + q2*vn2 + q3*s2*sd + q4*sd*vn2;
        float gv   = q5 + q6*sd + q7*s2 + q8*vn2;
        so[g] = sout;
        vo[g] = gv*vd0; vo[64 + g] = gv*vd1; vo[128 + g] = gv*vd2;
        asm volatile("bar.sync %0, 64;" :: "r"(bar) : "memory");

        float sp = 0.f, vp0 = 0.f, vp1 = 0.f, vp2 = 0.f;
        #pragma unroll 8
        for (int f = 0; f < 64; f++) {
            float a  = so[f];
            float a0 = vo[f], a1 = vo[64 + f], a2 = vo[128 + f];
            float w1 = sWps[f*64 + g], w2 = sWpv[f*64 + g];
            sp += a * w1; vp0 += a0 * w2; vp1 += a1 * w2; vp2 += a2 * w2;
        }
        sp  = sp  * 0.125f + g_skip_s[n*64 + g];
        vp0 = vp0 * 0.125f + g_skip_v[0*NF + n*64 + g];
        vp1 = vp1 * 0.125f + g_skip_v[1*NF + n*64 + g];
        vp2 = vp2 * 0.125f + g_skip_v[2*NF + n*64 + g];

        float* mrow = out + NN + (size_t)n * 256;
        mrow[g] = sp;
        mrow[64 + g*3]     = vp0;
        mrow[64 + g*3 + 1] = vp1;
        mrow[64 + g*3 + 2] = vp2;

        red[g] = sp * __ldg(Wout + g);
        asm volatile("bar.sync %0, 64;" :: "r"(bar) : "memory");
        if (g == 0) {
            float t2 = 0.f;
            #pragma unroll
            for (int i = 0; i < 64; i++) t2 += red[i];
            out[n] = t2 * 0.125f;
        }
        asm volatile("bar.sync %0, 64;" :: "r"(bar) : "memory");
    }
}

// ---------------- launch ----------------
extern "C" void kernel_launch(void* const* d_in, const int* in_sizes, int n_in,
                              void* d_out, int out_size) {
    const float* vectors    = (const float*)d_in[0];
    const float* node_feats = (const float*)d_in[1];
    const float* re         = (const float*)d_in[2];
    const float* Wss        = (const float*)d_in[3];
    const float* Wsv        = (const float*)d_in[4];
    const float* Wus        = (const float*)d_in[5];
    const float* Wuv        = (const float*)d_in[6];
    const float* W1         = (const float*)d_in[7];
    const float* W2         = (const float*)d_in[8];
    const float* W3         = (const float*)d_in[9];
    const float* W4         = (const float*)d_in[10];
    const float* Wds        = (const float*)d_in[11];
    const float* Wdv        = (const float*)d_in[12];
    const float* Wsc        = (const float*)d_in[13];
    const float* Wps        = (const float*)d_in[14];
    const float* Wpv        = (const float*)d_in[15];
    const float* Wout       = (const float*)d_in[16];
    const int*   species    = (const int*)d_in[17];
    const int*   senders    = (const int*)d_in[18];
    const int*   receivers  = (const int*)d_in[19];
    float* out = (float*)d_out;

    const int MLP_SMEM  = MLP_SMEM_FLOATS * 4;    // 192512 B
    const int POST_SMEM = POST_SMEM_FLOATS * 4;   // 83968 B
    cudaFuncSetAttribute(mlp_kernel, cudaFuncAttributeMaxDynamicSharedMemorySize, MLP_SMEM);
    cudaFuncSetAttribute(node_post,  cudaFuncAttributeMaxDynamicSharedMemorySize, POST_SMEM);

    zero_agg<<<2048, 256>>>();
    convert_skip<<<(ZZ*4096 + 255)/256, 256>>>(Wss, Wsv);
    node_pre<<<444, 512>>>(node_feats, Wus, Wuv, species);
    mlp_kernel<<<EE/256, 512, MLP_SMEM>>>(re, W1, W2, W3, W4);
    tp_scatter<<<EE*64/256, 256>>>(vectors, senders, receivers);
    node_post<<<296, 512, POST_SMEM>>>(Wds, Wdv, Wsc, Wps, Wpv, Wout, species, out);
}

// round 16
// speedup vs baseline: 1.1596x; 1.1596x over previous
#include <cuda_runtime.h>
#include <cuda_fp16.h>
#include <math.h>

#define NN 32768
#define EE 262144
#define FF 64
#define PSC 9
#define ZZ 10
#define NF (NN*FF)
#define HS 65   // 8*65 mod 32 = 8 -> 4 ei-groups hit banks {0,8,16,24}: conflict-free h loads

typedef unsigned long long u64;

// ---------------- device scratch ----------------
__device__ float g_skip_s[NF];
__device__ float g_skip_v[3*NF];
__device__ float g_sup[NF];
__device__ float g_vup[3*NF];
__device__ float g_agg_s[NF];
__device__ float g_agg_v[3*NF];
__device__ __half g_wh[(size_t)EE*320];   // per-edge TP path weights [E,5,64], fp16
__device__ __half g_wssh[ZZ*4096];        // fp16 per-species skip weights
__device__ __half g_wsvh[ZZ*4096];

// ---------------- f32x2 packed-math helpers ----------------
__device__ __forceinline__ u64 pack2(float x) {
    u64 r; asm("mov.b64 %0, {%1, %1};" : "=l"(r) : "f"(x)); return r;
}
__device__ __forceinline__ u64 packf2(float x, float y) {
    u64 r; asm("mov.b64 %0, {%1, %2};" : "=l"(r) : "f"(x), "f"(y)); return r;
}
__device__ __forceinline__ u64 fma2(u64 a, u64 b, u64 c) {
    u64 d; asm("fma.rn.f32x2 %0, %1, %2, %3;" : "=l"(d) : "l"(a), "l"(b), "l"(c)); return d;
}
__device__ __forceinline__ float2 unpk(u64 a) {
    float2 f; asm("mov.b64 {%0, %1}, %2;" : "=f"(f.x), "=f"(f.y) : "l"(a)); return f;
}
__device__ __forceinline__ float silu(float x) { return x / (1.f + __expf(-x)); }

__global__ void zero_agg() {
    int stride = gridDim.x * blockDim.x;
    int t = blockIdx.x * blockDim.x + threadIdx.x;
    for (int i = t; i < NF; i += stride) g_agg_s[i] = 0.f;
    for (int i = t; i < 3*NF; i += stride) g_agg_v[i] = 0.f;
}

__global__ void convert_skip(const float* __restrict__ Wss, const float* __restrict__ Wsv) {
    int i = blockIdx.x * 256 + threadIdx.x;
    if (i < ZZ*4096) {
        g_wssh[i] = __float2half(Wss[i]);
        g_wsvh[i] = __float2half(Wsv[i]);
    }
}

// ---------------- kernel A: per-species skip linear (fp16 weights) + linear_up (R14 exact) ----------------
__global__ void __launch_bounds__(512)
node_pre(const float* __restrict__ nf,
         const float* __restrict__ Wus,
         const float* __restrict__ Wuv,
         const int*   __restrict__ species) {
    __shared__ float sWus[FF*FF], sWuv[FF*FF];
    __shared__ float s_sh[8][FF];
    __shared__ float v_sh[8][3*FF];
    int tid = threadIdx.x;
    for (int i = tid; i < FF*FF; i += 512) { sWus[i] = Wus[i]; sWuv[i] = Wuv[i]; }
    __syncthreads();
    int g = tid & 63, grp = tid >> 6;
    int bar = grp + 1;
    int group_id = blockIdx.x * 8 + grp;
    int totalGroups = gridDim.x * 8;
    for (int n = group_id; n < NN; n += totalGroups) {
        const float* row = nf + (size_t)n * 256;
        s_sh[grp][g]        = row[g];
        v_sh[grp][g]        = row[64 + g];
        v_sh[grp][64 + g]   = row[128 + g];
        v_sh[grp][128 + g]  = row[192 + g];
        asm volatile("bar.sync %0, 64;" :: "r"(bar) : "memory");
        int z = species[n];
        const __half* wssz = g_wssh + z * 4096;
        const __half* wsvz = g_wsvh + z * 4096;
        float ks = 0.f, kv0 = 0.f, kv1 = 0.f, kv2 = 0.f;
        float us = 0.f, uv0 = 0.f, uv1 = 0.f, uv2 = 0.f;
        #pragma unroll 8
        for (int f = 0; f < FF; f++) {
            float sv = s_sh[grp][f];
            float a0 = v_sh[grp][f*3], a1 = v_sh[grp][f*3+1], a2 = v_sh[grp][f*3+2];
            float w1 = __half2float(__ldg(wssz + f*64 + g));
            float w2 = __half2float(__ldg(wsvz + f*64 + g));
            float w3 = sWus[f*64 + g];
            float w4 = sWuv[f*64 + g];
            ks  += sv * w1; kv0 += a0 * w2; kv1 += a1 * w2; kv2 += a2 * w2;
            us  += sv * w3; uv0 += a0 * w4; uv1 += a1 * w4; uv2 += a2 * w4;
        }
        const float invZ = 0.039528471f;
        const float inv  = 0.125f;
        g_skip_s[n*64 + g]          = ks  * invZ;
        g_skip_v[0*NF + n*64 + g]   = kv0 * invZ;
        g_skip_v[1*NF + n*64 + g]   = kv1 * invZ;
        g_skip_v[2*NF + n*64 + g]   = kv2 * invZ;
        g_sup[n*64 + g]             = us  * inv;
        g_vup[0*NF + n*64 + g]      = uv0 * inv;
        g_vup[1*NF + n*64 + g]      = uv1 * inv;
        g_vup[2*NF + n*64 + g]      = uv2 * inv;
        asm volatile("bar.sync %0, 64;" :: "r"(bar) : "memory");
    }
}

// ---------------- kernel B1: radial MLP, E=8 micro-tile, fp16 weights in smem ----------------
// smem bytes: sW1 fp32 2048 | sW2h 8192 | sW3h 8192 | sW4h 40960 | h 512*HS*4 (133120) = 192512
#define MLP_SMEM_BYTES (2048 + 8192 + 8192 + 40960 + 512*HS*4)

__device__ __forceinline__ void zacc8(u64 acc[4][8]) {
    #pragma unroll
    for (int gp = 0; gp < 4; gp++)
        #pragma unroll
        for (int ee = 0; ee < 8; ee++) acc[gp][ee] = 0ull;
}

// one k-step: 8 scalar h loads (conflict-free), 1 LDS.128 of 8 fp16 weights, 32 FFMA2
__device__ __forceinline__ void kstep8(const float* __restrict__ h, int e0, int k,
                                       const __half* __restrict__ wrow, u64 acc[4][8]) {
    u64 hp[8];
    #pragma unroll
    for (int ee = 0; ee < 8; ee++) hp[ee] = pack2(h[(e0+ee)*HS + k]);
    uint4 wpk = *(const uint4*)(wrow);
    u64 w[4];
    {
        const __half2* p = (const __half2*)&wpk;
        #pragma unroll
        for (int j = 0; j < 4; j++) {
            float2 f2 = __half22float2(p[j]);
            w[j] = packf2(f2.x, f2.y);
        }
    }
    #pragma unroll
    for (int gp = 0; gp < 4; gp++)
        #pragma unroll
        for (int ee = 0; ee < 8; ee++)
            acc[gp][ee] = fma2(hp[ee], w[gp], acc[gp][ee]);
}

__device__ __forceinline__ void write_silu8(u64 acc[4][8], float* h, int e0, int g0, float scale) {
    #pragma unroll
    for (int ee = 0; ee < 8; ee++) {
        float* dst = h + (e0+ee)*HS + g0;
        #pragma unroll
        for (int gp = 0; gp < 4; gp++) {
            float2 t = unpk(acc[gp][ee]);
            dst[gp*2]     = silu(t.x*scale);
            dst[gp*2 + 1] = silu(t.y*scale);
        }
    }
}

__global__ void __launch_bounds__(512)
mlp_kernel(const float* __restrict__ re,
           const float* __restrict__ W1,
           const float* __restrict__ W2,
           const float* __restrict__ W3,
           const float* __restrict__ W4) {
    extern __shared__ char smc[];
    float*  sW1  = (float*)smc;                   // 512 floats
    __half* sW2h = (__half*)(smc + 2048);         // 4096 halfs
    __half* sW3h = (__half*)(smc + 10240);
    __half* sW4h = (__half*)(smc + 18432);        // 20480 halfs
    float*  h    = (float*)(smc + 59392);         // 512*HS floats
    int tid = threadIdx.x;
    for (int i = tid; i < 512;   i += 512) sW1[i] = W1[i];
    for (int i = tid; i < 4096;  i += 512) { sW2h[i] = __float2half(W2[i]); sW3h[i] = __float2half(W3[i]); }
    for (int i = tid; i < 20480; i += 512) sW4h[i] = __float2half(W4[i]);
    __syncthreads();

    int e_base = blockIdx.x * 512;
    int cj = tid & 7, ei = tid >> 3;     // ei in [0,64)
    int g0 = cj * 8, e0 = ei * 8;

    u64 acc[4][8];

    // layer 1: K=8, re direct from gmem (addresses dedup'd across the 8 cj lanes)
    zacc8(acc);
    #pragma unroll
    for (int k = 0; k < 8; k++) {
        u64 hp[8];
        #pragma unroll
        for (int ee = 0; ee < 8; ee++)
            hp[ee] = pack2(__ldg(re + (size_t)(e_base + e0 + ee)*8 + k));
        ulonglong2 wa = *(const ulonglong2*)(sW1 + k*64 + g0);
        ulonglong2 wb = *(const ulonglong2*)(sW1 + k*64 + g0 + 4);
        u64 w0 = wa.x, w1 = wa.y, w2 = wb.x, w3 = wb.y;
        #pragma unroll
        for (int ee = 0; ee < 8; ee++) {
            acc[0][ee] = fma2(hp[ee], w0, acc[0][ee]);
            acc[1][ee] = fma2(hp[ee], w1, acc[1][ee]);
            acc[2][ee] = fma2(hp[ee], w2, acc[2][ee]);
            acc[3][ee] = fma2(hp[ee], w3, acc[3][ee]);
        }
    }
    write_silu8(acc, h, e0, g0, 0.35355339f);   // 1/sqrt(8)
    __syncthreads();

    // layer 2: in-place (all reads complete -> barrier -> write -> barrier)
    zacc8(acc);
    #pragma unroll 4
    for (int k = 0; k < 64; k++) kstep8(h, e0, k, sW2h + k*64 + g0, acc);
    __syncthreads();
    write_silu8(acc, h, e0, g0, 0.125f);
    __syncthreads();

    // layer 3: in-place
    zacc8(acc);
    #pragma unroll 4
    for (int k = 0; k < 64; k++) kstep8(h, e0, k, sW3h + k*64 + g0, acc);
    __syncthreads();
    write_silu8(acc, h, e0, g0, 0.125f);
    __syncthreads();

    // layer 4: 5 path slices, write g_wh (fp16)
    #pragma unroll
    for (int p = 0; p < 5; p++) {
        zacc8(acc);
        #pragma unroll 4
        for (int k = 0; k < 64; k++) kstep8(h, e0, k, sW4h + k*320 + p*64 + g0, acc);
        #pragma unroll
        for (int ee = 0; ee < 8; ee++) {
            float2 a = unpk(acc[0][ee]), b = unpk(acc[1][ee]);
            float2 c = unpk(acc[2][ee]), d = unpk(acc[3][ee]);
            __half2 h0 = __floats2half2_rn(a.x*0.125f, a.y*0.125f);
            __half2 h1 = __floats2half2_rn(b.x*0.125f, b.y*0.125f);
            __half2 h2 = __floats2half2_rn(c.x*0.125f, c.y*0.125f);
            __half2 h3 = __floats2half2_rn(d.x*0.125f, d.y*0.125f);
            uint4 pk;
            pk.x = *(unsigned*)&h0; pk.y = *(unsigned*)&h1;
            pk.z = *(unsigned*)&h2; pk.w = *(unsigned*)&h3;
            *(uint4*)(g_wh + (size_t)(e_base + e0 + ee)*320 + p*64 + g0) = pk;
        }
    }
}

// ---------------- kernel B2: tensor product + scatter (R13 exact) ----------------
__global__ void tp_scatter(const float* __restrict__ vectors,
                           const int* __restrict__ senders,
                           const int* __restrict__ receivers) {
    int t = blockIdx.x * 256 + threadIdx.x;
    int e = t >> 6, g = t & 63;
    float vx = __ldg(vectors + e*3), vy = __ldg(vectors + e*3 + 1), vz = __ldg(vectors + e*3 + 2);
    float rn = 1.f / (sqrtf(vx*vx + vy*vy + vz*vz) + 1e-9f);
    float y0 = vx * rn, y1 = vy * rn, y2 = vz * rn;

    const __half* wrow = g_wh + (size_t)e*320 + g;
    float w0  = __half2float(wrow[0]);
    float w1a = __half2float(wrow[64]);
    float w2a = __half2float(wrow[128]);
    float w3a = __half2float(wrow[192]);
    float w4a = __half2float(wrow[256]);

    int sn = __ldg(senders + e), rc = __ldg(receivers + e);
    float ss = g_sup[sn*64 + g];
    float b0 = g_vup[0*NF + sn*64 + g];
    float b1 = g_vup[1*NF + sn*64 + g];
    float b2 = g_vup[2*NF + sn*64 + g];
    float dot = b0*y0 + b1*y1 + b2*y2;
    float c0 = b1*y2 - b2*y1;
    float c1 = b2*y0 - b0*y2;
    float c2 = b0*y1 - b1*y0;
    const float is2 = 0.70710678f;
    float ms  = (w0*ss + w3a*dot) * 0.25f;
    float mv0 = (w1a*y0 + w2a*b0 + w4a*c0*is2) * 0.25f;
    float mv1 = (w1a*y1 + w2a*b1 + w4a*c1*is2) * 0.25f;
    float mv2 = (w1a*y2 + w2a*b2 + w4a*c2*is2) * 0.25f;
    atomicAdd(&g_agg_s[rc*64 + g], ms);
    atomicAdd(&g_agg_v[0*NF + rc*64 + g], mv0);
    atomicAdd(&g_agg_v[1*NF + rc*64 + g], mv1);
    atomicAdd(&g_agg_v[2*NF + rc*64 + g], mv2);
}

// ---------------- kernel C: node_post (R8 exact, 512 thr) ----------------
#define POST_SMEM_FLOATS (4*4096 + 8*576)
__global__ void __launch_bounds__(512)
node_post(const float* __restrict__ Wds,
          const float* __restrict__ Wdv,
          const float* __restrict__ Wsc,
          const float* __restrict__ Wps,
          const float* __restrict__ Wpv,
          const float* __restrict__ Wout,
          const int*   __restrict__ species,
          float* __restrict__ out) {
    extern __shared__ float sm[];
    float* sWds = sm;
    float* sWdv = sm + 4096;
    float* sWps = sm + 8192;
    float* sWpv = sm + 12288;
    float* buf  = sm + 16384;
    int tid = threadIdx.x;
    for (int i = tid; i < 4096; i += 512) {
        sWds[i] = Wds[i]; sWdv[i] = Wdv[i]; sWps[i] = Wps[i]; sWpv[i] = Wpv[i];
    }
    __syncthreads();
    int g = tid & 63, grp = tid >> 6, bar = grp + 1;
    float* ags = buf + grp * 576;
    float* agv = ags + 64;
    float* so  = agv + 192;
    float* vo  = so + 64;
    float* red = vo + 192;
    int group_id = blockIdx.x * 8 + grp;
    int totalGroups = gridDim.x * 8;
    for (int n = group_id; n < NN; n += totalGroups) {
        ags[g]       = g_agg_s[n*64 + g];
        agv[g]       = g_agg_v[0*NF + n*64 + g];
        agv[64 + g]  = g_agg_v[1*NF + n*64 + g];
        agv[128 + g] = g_agg_v[2*NF + n*64 + g];
        asm volatile("bar.sync %0, 64;" :: "r"(bar) : "memory");

        float sd = 0.f, vd0 = 0.f, vd1 = 0.f, vd2 = 0.f;
        #pragma unroll 8
        for (int f = 0; f < 64; f++) {
            float a  = ags[f];
            float a0 = agv[f], a1 = agv[64 + f], a2 = agv[128 + f];
            float w1 = sWds[f*64 + g], w2 = sWdv[f*64 + g];
            sd += a * w1; vd0 += a0 * w2; vd1 += a1 * w2; vd2 += a2 * w2;
        }
        sd *= 0.125f; vd0 *= 0.125f; vd1 *= 0.125f; vd2 *= 0.125f;

        int z = species[n];
        const float* wz = Wsc + z * (PSC*64) + g;
        float q0 = __ldg(wz),       q1 = __ldg(wz + 64),  q2 = __ldg(wz + 128);
        float q3 = __ldg(wz + 192), q4 = __ldg(wz + 256), q5 = __ldg(wz + 320);
        float q6 = __ldg(wz + 384), q7 = __ldg(wz + 448), q8 = __ldg(wz + 512);
        float vn2 = vd0*vd0 + vd1*vd1 + vd2*vd2;
        float s2  = sd * sd;
        float sout = q0*sd + q1*s2 + q2*vn2 + q3*s2*sd + q4*sd*vn2;
        float gv   = q5 + q6*sd + q7*s2 + q8*vn2;
        so[g] = sout;
        vo[g] = gv*vd0; vo[64 + g] = gv*vd1; vo[128 + g] = gv*vd2;
        asm volatile("bar.sync %0, 64;" :: "r"(bar) : "memory");

        float sp = 0.f, vp0 = 0.f, vp1 = 0.f, vp2 = 0.f;
        #pragma unroll 8
        for (int f = 0; f < 64; f++) {
            float a  = so[f];
            float a0 = vo[f], a1 = vo[64 + f], a2 = vo[128 + f];
            float w1 = sWps[f*64 + g], w2 = sWpv[f*64 + g];
            sp += a * w1; vp0 += a0 * w2; vp1 += a1 * w2; vp2 += a2 * w2;
        }
        sp  = sp  * 0.125f + g_skip_s[n*64 + g];
        vp0 = vp0 * 0.125f + g_skip_v[0*NF + n*64 + g];
        vp1 = vp1 * 0.125f + g_skip_v[1*NF + n*64 + g];
        vp2 = vp2 * 0.125f + g_skip_v[2*NF + n*64 + g];

        float* mrow = out + NN + (size_t)n * 256;
        mrow[g] = sp;
        mrow[64 + g*3]     = vp0;
        mrow[64 + g*3 + 1] = vp1;
        mrow[64 + g*3 + 2] = vp2;

        red[g] = sp * __ldg(Wout + g);
        asm volatile("bar.sync %0, 64;" :: "r"(bar) : "memory");
        if (g == 0) {
            float t2 = 0.f;
            #pragma unroll
            for (int i = 0; i < 64; i++) t2 += red[i];
            out[n] = t2 * 0.125f;
        }
        asm volatile("bar.sync %0, 64;" :: "r"(bar) : "memory");
    }
}

// ---------------- launch ----------------
extern "C" void kernel_launch(void* const* d_in, const int* in_sizes, int n_in,
                              void* d_out, int out_size) {
    const float* vectors    = (const float*)d_in[0];
    const float* node_feats = (const float*)d_in[1];
    const float* re         = (const float*)d_in[2];
    const float* Wss        = (const float*)d_in[3];
    const float* Wsv        = (const float*)d_in[4];
    const float* Wus        = (const float*)d_in[5];
    const float* Wuv        = (const float*)d_in[6];
    const float* W1         = (const float*)d_in[7];
    const float* W2         = (const float*)d_in[8];
    const float* W3         = (const float*)d_in[9];
    const float* W4         = (const float*)d_in[10];
    const float* Wds        = (const float*)d_in[11];
    const float* Wdv        = (const float*)d_in[12];
    const float* Wsc        = (const float*)d_in[13];
    const float* Wps        = (const float*)d_in[14];
    const float* Wpv        = (const float*)d_in[15];
    const float* Wout       = (const float*)d_in[16];
    const int*   species    = (const int*)d_in[17];
    const int*   senders    = (const int*)d_in[18];
    const int*   receivers  = (const int*)d_in[19];
    float* out = (float*)d_out;

    const int POST_SMEM = POST_SMEM_FLOATS * 4;   // 83968 B
    cudaFuncSetAttribute(mlp_kernel, cudaFuncAttributeMaxDynamicSharedMemorySize, MLP_SMEM_BYTES);
    cudaFuncSetAttribute(node_post,  cudaFuncAttributeMaxDynamicSharedMemorySize, POST_SMEM);

    zero_agg<<<2048, 256>>>();
    convert_skip<<<(ZZ*4096 + 255)/256, 256>>>(Wss, Wsv);
    node_pre<<<444, 512>>>(node_feats, Wus, Wuv, species);
    mlp_kernel<<<EE/512, 512, MLP_SMEM_BYTES>>>(re, W1, W2, W3, W4);
    tp_scatter<<<EE*64/256, 256>>>(vectors, senders, receivers);
    node_post<<<296, 512, POST_SMEM>>>(Wds, Wdv, Wsc, Wps, Wpv, Wout, species, out);
}